// round 10
// baseline (speedup 1.0000x reference)
#include <cuda_runtime.h>

#define NN 8192
#define EE 16384

// u = e .* (Ro^T a) in g_uv[0..EE), v = e .* (Ri^T b) in g_uv[EE..2EE).
__device__ float g_uv[2 * EE];
__device__ unsigned int g_ticket;   // phase2 tile dispatcher

// ---------------- Phase 1: column reductions (UNCHANGED — 6.85 TB/s) -------
// u[e] = ev[e] * sum_n Ro[n,e]*a[n],  v[e] = ev[e] * sum_n Ri[n,e]*b[n]
#define P1_CHUNK 128
#define P1_NCHUNK (NN / P1_CHUNK)      // 64
#define P1_KEEP 8
__global__ __launch_bounds__(256) void phase1(
    const float4* __restrict__ X4, const float* __restrict__ ker,
    const float* __restrict__ Ri, const float* __restrict__ Ro,
    const float* __restrict__ ev)
{
    __shared__ float sa[P1_CHUNK], sb[P1_CHUNK];
    int tid = threadIdx.x;
    int e   = blockIdx.x * 256 + tid;
    int yc  = blockIdx.y;
    int n0  = (P1_NCHUNK - 1 - yc) * P1_CHUNK;   // reversed row mapping

    if (tid < P1_CHUNK) {
        float4 x = X4[n0 + tid];
        sa[tid] = x.x * ker[0] + x.y * ker[1] + x.z * ker[2] + x.w * ker[3];
        sb[tid] = x.x * ker[4] + x.y * ker[5] + x.z * ker[6] + x.w * ker[7];
    }
    __syncthreads();

    const float* ro = Ro + (size_t)n0 * EE + e;
    const float* ri = Ri + (size_t)n0 * EE + e;
    float so = 0.0f, si = 0.0f;

    if (yc >= P1_NCHUNK - P1_KEEP) {
#pragma unroll 8
        for (int j = 0; j < P1_CHUNK; j++) {
            so += ro[(size_t)j * EE] * sa[j];
            si += ri[(size_t)j * EE] * sb[j];
        }
    } else {
#pragma unroll 8
        for (int j = 0; j < P1_CHUNK; j++) {
            so += __ldcs(ro + (size_t)j * EE) * sa[j];
            si += __ldcs(ri + (size_t)j * EE) * sb[j];
        }
    }
    float w = ev[e];
    atomicAdd(&g_uv[e],      w * so);
    atomicAdd(&g_uv[EE + e], w * si);
}

// ---------------- Phase 2: row reductions (R8 shape, SCALAR loads) ---------
// out[n] = sum_e Ri[n,e]*u[e] + Ro[n,e]*v[e] + X[n].k2
// One change vs R8: LDG.32 instead of LDG.128 — one clean 128B wavefront per
// warp load (no within-LDG replays in L1tex), matching phase1's load width.
#define RPB 4
#define NTILES (NN / RPB)              // 2048
#define P2_BLOCKS (148 * 4)
__global__ __launch_bounds__(256) void phase2(
    const float4* __restrict__ X4, const float* __restrict__ ker,
    const float* __restrict__ Ri, const float* __restrict__ Ro,
    float* __restrict__ out)
{
    __shared__ float red[RPB][256];
    __shared__ int sTile;
    int tid = threadIdx.x;

    const float* u = g_uv;
    const float* v = g_uv + EE;

    for (;;) {
        if (tid == 0) sTile = (int)atomicAdd(&g_ticket, 1u);
        __syncthreads();
        int tile = sTile;
        if (tile >= NTILES) break;
        int n0 = tile * RPB;

        const float* r0 = Ri + (size_t)n0 * EE;
        const float* o0 = Ro + (size_t)n0 * EE;

        float s[RPB];
#pragma unroll
        for (int r = 0; r < RPB; r++) s[r] = 0.0f;

#pragma unroll 4
        for (int it = 0; it < EE / 256; it++) {
            int e = it * 256 + tid;
            float ue = u[e];               // L2-hot (128 KB total)
            float ve = v[e];
#pragma unroll
            for (int r = 0; r < RPB; r++) {
                float a = __ldcs(r0 + (size_t)r * EE + e);
                float b = __ldcs(o0 + (size_t)r * EE + e);
                s[r] += a * ue + b * ve;
            }
        }

#pragma unroll
        for (int r = 0; r < RPB; r++) red[r][tid] = s[r];
        __syncthreads();
        for (int st = 128; st > 0; st >>= 1) {
            if (tid < st) {
#pragma unroll
                for (int r = 0; r < RPB; r++) red[r][tid] += red[r][tid + st];
            }
            __syncthreads();
        }
        if (tid < RPB) {
            float4 x = X4[n0 + tid];
            out[n0 + tid] = red[tid][0]
                          + x.x * ker[8] + x.y * ker[9] + x.z * ker[10] + x.w * ker[11];
        }
        __syncthreads();
    }
}

extern "C" void kernel_launch(void* const* d_in, const int* in_sizes, int n_in,
                              void* d_out, int out_size) {
    const float4* X4  = (const float4*)d_in[0];
    const float*  ev  = (const float*)d_in[1];
    const float*  Ri  = (const float*)d_in[2];
    const float*  Ro  = (const float*)d_in[3];
    const float*  ker = (const float*)d_in[4];
    float* out = (float*)d_out;

    void* uvptr = nullptr;
    cudaGetSymbolAddress(&uvptr, g_uv);
    cudaMemsetAsync(uvptr, 0, 2 * EE * sizeof(float));
    void* tkptr = nullptr;
    cudaGetSymbolAddress(&tkptr, g_ticket);
    cudaMemsetAsync(tkptr, 0, sizeof(unsigned int));

    dim3 g1(EE / 256, P1_NCHUNK);                  // (64, 64)
    phase1<<<g1, 256>>>(X4, ker, Ri, Ro, ev);

    phase2<<<P2_BLOCKS, 256>>>(X4, ker, Ri, Ro, out);
}

// round 11
// speedup vs baseline: 1.7649x; 1.7649x over previous
#include <cuda_runtime.h>

#define NN 8192
#define EE 16384
#define EE4 (EE / 4)

// g_uv[0..EE) = u = e.*(Ro^T a);  g_uv[EE..2EE) = v = e.*(Ri^T b)
__device__ float g_uv[2 * EE];
__device__ unsigned int g_ticket;   // phase C tile dispatcher

// ---------------- Phase A: u from Ro (column reduce, proven shape) ---------
// u[e] = ev[e] * sum_n Ro[n,e]*a[n],  a = X.k0 inline.
#define PA_CHUNK 128
__global__ __launch_bounds__(256) void phaseA(
    const float4* __restrict__ X4, const float* __restrict__ ker,
    const float* __restrict__ Ro, const float* __restrict__ ev)
{
    __shared__ float sa[PA_CHUNK];
    int tid = threadIdx.x;
    int e   = blockIdx.x * 256 + tid;
    int n0  = blockIdx.y * PA_CHUNK;

    if (tid < PA_CHUNK) {
        float4 x = X4[n0 + tid];
        sa[tid] = x.x * ker[0] + x.y * ker[1] + x.z * ker[2] + x.w * ker[3];
    }
    __syncthreads();

    const float* ro = Ro + (size_t)n0 * EE + e;
    float so = 0.0f;
#pragma unroll 8
    for (int j = 0; j < PA_CHUNK; j++)
        so += __ldcs(ro + (size_t)j * EE) * sa[j];

    atomicAdd(&g_uv[e], ev[e] * so);
}

// ---------------- Phase B: single pass over Ri -----------------------------
// One load of Ri[n,e] feeds BOTH:
//   v[e]   += Ri[n,e] * b[n]          (column reduce, register accum + atomic)
//   out[n] += Ri[n,e] * u[e]          (row reduce: warp shfl butterfly ->
//                                      shared -> one spread atomicAdd per row)
// Thread owns a float4 column group (LDG.128 for bytes-in-flight), block =
// 1024 columns x 128 rows (512 KB of Ri).
__global__ __launch_bounds__(256) void phaseB(
    const float4* __restrict__ X4, const float* __restrict__ ker,
    const float4* __restrict__ Ri4, const float4* __restrict__ ev4,
    float* __restrict__ out)
{
    __shared__ float sb[128];
    __shared__ float sred[128][8];
    int tid  = threadIdx.x;
    int lane = tid & 31;
    int wid  = tid >> 5;
    int e4   = blockIdx.x * 256 + tid;      // float4 column index
    int n0   = blockIdx.y * 128;

    if (tid < 128) {
        float4 x = X4[n0 + tid];
        sb[tid] = x.x * ker[4] + x.y * ker[5] + x.z * ker[6] + x.w * ker[7];
    }
    __syncthreads();

    float4 u = *reinterpret_cast<const float4*>(&g_uv[4 * e4]);   // final after A
    float4 si = make_float4(0.f, 0.f, 0.f, 0.f);
    const float4* ri = Ri4 + (size_t)n0 * EE4 + e4;

#pragma unroll 4
    for (int j = 0; j < 128; j++) {
        float4 t = __ldcs(ri + (size_t)j * EE4);
        float B = sb[j];
        si.x += t.x * B; si.y += t.y * B; si.z += t.z * B; si.w += t.w * B;
        float r = t.x * u.x + t.y * u.y + t.z * u.z + t.w * u.w;
        r += __shfl_xor_sync(0xffffffffu, r, 16);
        r += __shfl_xor_sync(0xffffffffu, r, 8);
        r += __shfl_xor_sync(0xffffffffu, r, 4);
        r += __shfl_xor_sync(0xffffffffu, r, 2);
        r += __shfl_xor_sync(0xffffffffu, r, 1);
        if (lane == 0) sred[j][wid] = r;
    }

    float4 w = ev4[e4];
    int e = 4 * e4;
    atomicAdd(&g_uv[EE + e + 0], w.x * si.x);
    atomicAdd(&g_uv[EE + e + 1], w.y * si.y);
    atomicAdd(&g_uv[EE + e + 2], w.z * si.z);
    atomicAdd(&g_uv[EE + e + 3], w.w * si.w);

    __syncthreads();
    if (tid < 128) {
        float val = sred[tid][0] + sred[tid][1] + sred[tid][2] + sred[tid][3]
                  + sred[tid][4] + sred[tid][5] + sred[tid][6] + sred[tid][7];
        atomicAdd(&out[n0 + tid], val);
    }
}

// ---------------- Phase C: out += Ro.v + c (row reduce, R8-proven shape) ---
#define RPB 4
#define NTILES (NN / RPB)
#define PC_BLOCKS (148 * 4)
__global__ __launch_bounds__(256) void phaseC(
    const float4* __restrict__ X4, const float* __restrict__ ker,
    const float4* __restrict__ Ro4, float* __restrict__ out)
{
    __shared__ float red[RPB][256];
    __shared__ int sTile;
    int tid = threadIdx.x;

    const float4* v4 = reinterpret_cast<const float4*>(g_uv) + EE4;

    for (;;) {
        if (tid == 0) sTile = (int)atomicAdd(&g_ticket, 1u);
        __syncthreads();
        int tile = sTile;
        if (tile >= NTILES) break;
        int n0 = tile * RPB;

        float s[RPB];
#pragma unroll
        for (int r = 0; r < RPB; r++) s[r] = 0.0f;

#pragma unroll 4
        for (int it = 0; it < EE4 / 256; it++) {
            int e4 = it * 256 + tid;
            float4 v = v4[e4];                 // L2-hot (64 KB)
#pragma unroll
            for (int r = 0; r < RPB; r++) {
                float4 b = __ldcs(Ro4 + (size_t)(n0 + r) * EE4 + e4);
                s[r] += b.x * v.x + b.y * v.y + b.z * v.z + b.w * v.w;
            }
        }

#pragma unroll
        for (int r = 0; r < RPB; r++) red[r][tid] = s[r];
        __syncthreads();
        for (int st = 128; st > 0; st >>= 1) {
            if (tid < st) {
#pragma unroll
                for (int r = 0; r < RPB; r++) red[r][tid] += red[r][tid + st];
            }
            __syncthreads();
        }
        if (tid < RPB) {
            int n = n0 + tid;
            float4 x = X4[n];
            out[n] = out[n] + red[tid][0]      // out already holds Ri.u from B
                   + x.x * ker[8] + x.y * ker[9] + x.z * ker[10] + x.w * ker[11];
        }
        __syncthreads();
    }
}

extern "C" void kernel_launch(void* const* d_in, const int* in_sizes, int n_in,
                              void* d_out, int out_size) {
    const float4* X4  = (const float4*)d_in[0];
    const float*  ev  = (const float*)d_in[1];
    const float*  Ri  = (const float*)d_in[2];
    const float*  Ro  = (const float*)d_in[3];
    const float*  ker = (const float*)d_in[4];
    float* out = (float*)d_out;

    void* uvptr = nullptr;
    cudaGetSymbolAddress(&uvptr, g_uv);
    cudaMemsetAsync(uvptr, 0, 2 * EE * sizeof(float));
    void* tkptr = nullptr;
    cudaGetSymbolAddress(&tkptr, g_ticket);
    cudaMemsetAsync(tkptr, 0, sizeof(unsigned int));
    cudaMemsetAsync(out, 0, (size_t)out_size * sizeof(float));

    dim3 gA(EE / 256, NN / PA_CHUNK);     // (64, 64)
    phaseA<<<gA, 256>>>(X4, ker, Ro, ev);

    dim3 gB(EE4 / 256, NN / 128);         // (16, 64)
    phaseB<<<gB, 256>>>(X4, ker, (const float4*)Ri, (const float4*)ev, out);

    phaseC<<<PC_BLOCKS, 256>>>(X4, ker, (const float4*)Ro, out);
}